// round 9
// baseline (speedup 1.0000x reference)
#include <cuda_runtime.h>
#include <cuda_bf16.h>
#include <cstdint>
#include <float.h>

// ---------------------------------------------------------------- problem dims
#define B_  32
#define D_  256
#define K_  8192
#define HW  1024
#define N_  32768
#define OUT_ELEMS 8388608
#define LOSS_OFF  OUT_ELEMS
#define IDX_OFF   (OUT_ELEMS + 1)

// ---------------------------------------------------------------- GEMM tiling
#define NCHUNK 64                    // 64 chunks of 128 codes
#define AS_STRIDE 264                // bf16 elems per A smem row (256 + 8 pad)
#define BS_STRIDE 136                // bf16 elems per B smem row (128 + 8 pad)
#define SM_A 0
#define SM_B (128 * AS_STRIDE * 2)   // 67584
#define BUFB (256 * BS_STRIDE * 2)   // 69632
#define SM_TOTAL (SM_B + 2 * BUFB)   // 206848

// ---------------------------------------------------------------- scratch
__device__ __align__(16) float g_enorm[K_];
__device__ __align__(16) int   g_idx[N_];
__device__ __align__(16) float g_part[1024];
__device__ __align__(16) int   g_top4[N_ * 4];
__device__ __align__(16) __nv_bfloat16 g_latT[(size_t)N_ * D_];   // [n][d] row-major
__device__ __align__(16) __nv_bfloat16 g_embBf[(size_t)D_ * K_];  // [d][k] row-major
__device__ __align__(16) float g_embT[(size_t)K_ * D_];           // [k][d] fp32

// ---------------------------------------------------------------- helpers
__device__ __forceinline__ uint32_t smem_u32(const void* p) {
    return (uint32_t)__cvta_generic_to_shared(p);
}
__device__ __forceinline__ void cp_async16(uint32_t dst, const void* src) {
    asm volatile("cp.async.cg.shared.global [%0], [%1], 16;" :: "r"(dst), "l"(src));
}
__device__ __forceinline__ void ldsm_x4(uint32_t* r, uint32_t addr) {
    asm volatile("ldmatrix.sync.aligned.m8n8.x4.shared.b16 {%0,%1,%2,%3}, [%4];"
                 : "=r"(r[0]), "=r"(r[1]), "=r"(r[2]), "=r"(r[3]) : "r"(addr));
}
__device__ __forceinline__ void ldsm_x4_t(uint32_t* r, uint32_t addr) {
    asm volatile("ldmatrix.sync.aligned.m8n8.x4.trans.shared.b16 {%0,%1,%2,%3}, [%4];"
                 : "=r"(r[0]), "=r"(r[1]), "=r"(r[2]), "=r"(r[3]) : "r"(addr));
}
__device__ __forceinline__ void mma_bf16(float* c, const uint32_t* a, uint32_t b0, uint32_t b1) {
    asm volatile(
        "mma.sync.aligned.m16n8k16.row.col.f32.bf16.bf16.f32 "
        "{%0,%1,%2,%3}, {%4,%5,%6,%7}, {%8,%9}, {%0,%1,%2,%3};"
        : "+f"(c[0]), "+f"(c[1]), "+f"(c[2]), "+f"(c[3])
        : "r"(a[0]), "r"(a[1]), "r"(a[2]), "r"(a[3]), "r"(b0), "r"(b1));
}

// ---------------------------------------------------------------- kernel 1: enorm
__global__ void enorm_kernel(const float* __restrict__ emb) {
    int k = blockIdx.x * blockDim.x + threadIdx.x;
    float s = 0.f;
#pragma unroll 8
    for (int d = 0; d < D_; ++d) {
        float v = emb[(size_t)d * K_ + k];
        s = fmaf(v, v, s);
    }
    g_enorm[k] = s;
}

// ---------------------------------------------------------------- kernel 2: latents -> bf16 [n][d]
__global__ void latconv_kernel(const float* __restrict__ lat) {
    __shared__ float t[32][33];
    int b = blockIdx.z, hw0 = blockIdx.x * 32, d0 = blockIdx.y * 32;
    t[threadIdx.y][threadIdx.x] =
        lat[((size_t)b * D_ + d0 + threadIdx.y) * HW + hw0 + threadIdx.x];
    __syncthreads();
    g_latT[((size_t)(b * HW + hw0 + threadIdx.y)) * D_ + d0 + threadIdx.x] =
        __float2bfloat16(t[threadIdx.x][threadIdx.y]);
}

// ---------------------------------------------------------------- kernel 3: embeddings -> bf16 [d][k]
__global__ void embconv_kernel(const float* __restrict__ emb) {
    size_t i = (size_t)blockIdx.x * blockDim.x + threadIdx.x;   // over D_*K_/4
    float4 v = reinterpret_cast<const float4*>(emb)[i];
    __nv_bfloat162 lo = __floats2bfloat162_rn(v.x, v.y);
    __nv_bfloat162 hi = __floats2bfloat162_rn(v.z, v.w);
    uint2 pk;
    pk.x = *reinterpret_cast<uint32_t*>(&lo);
    pk.y = *reinterpret_cast<uint32_t*>(&hi);
    reinterpret_cast<uint2*>(g_embBf)[i] = pk;
}

// ---------------------------------------------------------------- kernel 4: embeddings -> fp32 [k][d] (rescore + gather)
__global__ void embT_kernel(const float* __restrict__ emb) {
    __shared__ float t[32][33];
    int kb = blockIdx.x * 32, db = blockIdx.y * 32;
    t[threadIdx.y][threadIdx.x] = emb[(size_t)(db + threadIdx.y) * K_ + kb + threadIdx.x];
    __syncthreads();
    g_embT[(size_t)(kb + threadIdx.y) * D_ + db + threadIdx.x] = t[threadIdx.x][threadIdx.y];
}

// ---------------------------------------------------------------- kernel 5: bf16 mma.sync GEMM + per-row candidates
// 512 threads, 16 warps in 4(M) x 4(N); warp tile 32x32. 4 warps/SMSP so the
// scheduler can overlap one warp's MMAs with another's LDSM/epilogue.
__global__ __launch_bounds__(512, 1)
void vq_mma_kernel() {
    extern __shared__ char smem[];
    const uint32_t sb = smem_u32(smem);
    const int tid = threadIdx.x, lane = tid & 31, wid = tid >> 5;
    const int wm = wid & 3;        // 0-3: 32-row quarter
    const int wn = wid >> 2;       // 0-3: 32-col quarter

    // preload A tile (128 x 256 bf16, padded rows) + B chunk 0, one group
    {
        const char* at = (const char*)(g_latT + (size_t)blockIdx.x * 128 * D_);
        for (int i = tid; i < 4096; i += 512) {
            int r = i >> 5, s = i & 31;
            cp_async16(sb + SM_A + r * (AS_STRIDE * 2) + s * 16, at + r * 512 + s * 16);
        }
        const char* bt = (const char*)g_embBf;
        for (int i = tid; i < 4096; i += 512) {
            int r = i >> 4, s = i & 15;
            cp_async16(sb + SM_B + r * (BS_STRIDE * 2) + s * 16,
                       bt + (size_t)r * (K_ * 2) + s * 16);
        }
        asm volatile("cp.async.commit_group;" ::: "memory");
    }

    // per-lane ldmatrix base addresses: A rows wm*32..+32 (2 x 16-row frags)
    uint32_t a_addr[2];
#pragma unroll
    for (int mf = 0; mf < 2; ++mf)
        a_addr[mf] = sb + SM_A + (wm * 32 + mf * 16 + (lane & 15)) * (AS_STRIDE * 2)
                   + (lane >> 4) * 16;
    const uint32_t b_off = (((lane >> 3) & 1) * 8 + (lane & 7)) * (BS_STRIDE * 2)
                         + (wn * 32 + (lane >> 4) * 8) * 2;

    // per-(thread,row) top-2 over this thread's disjoint 512-col subset
    float sv[4][2];
    int   si[4][2];
#pragma unroll
    for (int r = 0; r < 4; ++r) { sv[r][0] = sv[r][1] = FLT_MAX; si[r][0] = si[r][1] = 0; }

    for (int u = 0; u < NCHUNK; ++u) {
        if (u + 1 < NCHUNK) {
            const char* bt = (const char*)g_embBf + (size_t)(u + 1) * 256;
            uint32_t bd = sb + SM_B + ((u + 1) & 1) * BUFB;
            for (int i = tid; i < 4096; i += 512) {
                int r = i >> 4, s = i & 15;
                cp_async16(bd + r * (BS_STRIDE * 2) + s * 16,
                           bt + (size_t)r * (K_ * 2) + s * 16);
            }
            asm volatile("cp.async.commit_group;" ::: "memory");
            asm volatile("cp.async.wait_group 1;" ::: "memory");
        } else {
            asm volatile("cp.async.wait_group 0;" ::: "memory");
        }
        __syncthreads();

        float acc[2][4][4];
#pragma unroll
        for (int mf = 0; mf < 2; ++mf)
#pragma unroll
            for (int nf = 0; nf < 4; ++nf)
#pragma unroll
                for (int q = 0; q < 4; ++q) acc[mf][nf][q] = 0.f;

        const uint32_t bbase = sb + SM_B + (u & 1) * BUFB + b_off;
#pragma unroll
        for (int ks = 0; ks < 16; ++ks) {
            uint32_t ar[2][4];
#pragma unroll
            for (int mf = 0; mf < 2; ++mf) ldsm_x4(ar[mf], a_addr[mf] + ks * 32);
            uint32_t br[2][4];
#pragma unroll
            for (int p = 0; p < 2; ++p)
                ldsm_x4_t(br[p], bbase + ks * 16 * (BS_STRIDE * 2) + p * 32);
#pragma unroll
            for (int mf = 0; mf < 2; ++mf)
#pragma unroll
                for (int nf = 0; nf < 4; ++nf)
                    mma_bf16(acc[mf][nf], ar[mf],
                             br[nf >> 1][(nf & 1) * 2], br[nf >> 1][(nf & 1) * 2 + 1]);
        }

        // epilogue: sc = enorm[c] - 2*dot; track top-2 per row subset.
        const int cb0 = (u << 7) + wn * 32 + (lane & 3) * 2;
#pragma unroll
        for (int nf = 0; nf < 4; ++nf) {
            const int c0 = cb0 + nf * 8;
            float2 e = __ldg(reinterpret_cast<const float2*>(&g_enorm[c0]));
#pragma unroll
            for (int mf = 0; mf < 2; ++mf) {
#pragma unroll
                for (int half = 0; half < 2; ++half) {
                    const int rs = mf * 2 + half;
                    float v0 = fmaf(-2.f, acc[mf][nf][half * 2 + 0], e.x);
                    float v1 = fmaf(-2.f, acc[mf][nf][half * 2 + 1], e.y);
                    if (v0 < sv[rs][1]) {
                        if (v0 < sv[rs][0]) { sv[rs][1] = sv[rs][0]; si[rs][1] = si[rs][0];
                                              sv[rs][0] = v0; si[rs][0] = c0; }
                        else                { sv[rs][1] = v0; si[rs][1] = c0; }
                    }
                    if (v1 < sv[rs][1]) {
                        if (v1 < sv[rs][0]) { sv[rs][1] = sv[rs][0]; si[rs][1] = si[rs][0];
                                              sv[rs][0] = v1; si[rs][0] = c0 + 1; }
                        else                { sv[rs][1] = v1; si[rs][1] = c0 + 1; }
                    }
                }
            }
        }
        __syncthreads();   // protect B buffer reuse by next prefetch
    }

    // merge: 16 subsets x top-2 = 32 candidates per row -> top-4
    struct Pair { float v; int i; };
    Pair* pr = reinterpret_cast<Pair*>(smem);   // [128][32], 32KB (A region, done)
    __syncthreads();
#pragma unroll
    for (int rs = 0; rs < 4; ++rs) {
        int r = wm * 32 + (rs >> 1) * 16 + (rs & 1) * 8 + (lane >> 2);
        int sub = wn * 4 + (lane & 3);
        pr[r * 32 + sub * 2 + 0] = { sv[rs][0], si[rs][0] };
        pr[r * 32 + sub * 2 + 1] = { sv[rs][1], si[rs][1] };
    }
    __syncthreads();
    if (tid < 128) {
        float bv[4] = {FLT_MAX, FLT_MAX, FLT_MAX, FLT_MAX};
        int   bi[4] = {0x7fffffff, 0x7fffffff, 0x7fffffff, 0x7fffffff};
        for (int j = 0; j < 32; ++j) {
            float v = pr[tid * 32 + j].v;
            int   i = pr[tid * 32 + j].i;
            if (v < bv[3] || (v == bv[3] && i < bi[3])) {
                if (v < bv[0] || (v == bv[0] && i < bi[0])) {
                    bv[3]=bv[2]; bi[3]=bi[2]; bv[2]=bv[1]; bi[2]=bi[1];
                    bv[1]=bv[0]; bi[1]=bi[0]; bv[0]=v; bi[0]=i;
                } else if (v < bv[1] || (v == bv[1] && i < bi[1])) {
                    bv[3]=bv[2]; bi[3]=bi[2]; bv[2]=bv[1]; bi[2]=bi[1];
                    bv[1]=v; bi[1]=i;
                } else if (v < bv[2] || (v == bv[2] && i < bi[2])) {
                    bv[3]=bv[2]; bi[3]=bi[2]; bv[2]=v; bi[2]=i;
                } else {
                    bv[3]=v; bi[3]=i;
                }
            }
        }
        int row = blockIdx.x * 128 + tid;
#pragma unroll
        for (int s = 0; s < 4; ++s) g_top4[row * 4 + s] = bi[s];
    }
}

// ---------------------------------------------------------------- kernel 6: exact fp32 rescore of top-4
__global__ __launch_bounds__(256)
void rescore_kernel(const float* __restrict__ lat, float* __restrict__ out_idx_f) {
    int row = blockIdx.x * 32 + (threadIdx.x >> 3);
    int l8  = threadIdx.x & 7;
    int b = row >> 10, hw = row & (HW - 1);
    const float* z = lat + (size_t)b * (D_ * HW) + hw;
    int cand[4];
#pragma unroll
    for (int c = 0; c < 4; ++c) cand[c] = g_top4[row * 4 + c];
    float dot[4] = {0.f, 0.f, 0.f, 0.f};
    for (int d = l8; d < D_; d += 8) {
        float zv = z[(size_t)d * HW];
#pragma unroll
        for (int c = 0; c < 4; ++c)
            dot[c] = fmaf(zv, g_embT[(size_t)cand[c] * D_ + d], dot[c]);
    }
#pragma unroll
    for (int c = 0; c < 4; ++c) {
#pragma unroll
        for (int off = 4; off > 0; off >>= 1)
            dot[c] += __shfl_down_sync(0xffffffffu, dot[c], off, 8);
    }
    if (l8 == 0) {
        float bv = FLT_MAX; int bi = 0x7fffffff;
#pragma unroll
        for (int c = 0; c < 4; ++c) {
            float dist = fmaf(-2.f, dot[c], g_enorm[cand[c]]);
            if (dist < bv || (dist == bv && cand[c] < bi)) { bv = dist; bi = cand[c]; }
        }
        g_idx[row] = bi;
        out_idx_f[row] = (float)bi;
    }
}

// ---------------------------------------------------------------- kernel 7: gather + loss, fully coalesced via embT + smem transpose
__global__ __launch_bounds__(256)
void gather_loss_kernel(const float* __restrict__ lat, float* __restrict__ out) {
    __shared__ float tile[32][257];   // [w][d], padded: stride 257 mod 32 = 1
    int bh = blockIdx.x;              // (b,h)
    int b = bh >> 5, h = bh & 31;
    int t = threadIdx.x;

    // load phase: row i's embedding vector, 256 consecutive floats per row
#pragma unroll 4
    for (int i = 0; i < 32; ++i) {
        int idx = g_idx[bh * 32 + i];
        tile[i][t] = g_embT[(size_t)idx * D_ + t];
    }
    __syncthreads();

    // write phase: coalesced over w; fuse squared-error partials
    size_t base = (size_t)b * (D_ * HW) + h * 32;
    int w = t & 31, d0 = t >> 5;
    float lsum = 0.f;
#pragma unroll 4
    for (int i = 0; i < 32; ++i) {
        int d = i * 8 + d0;
        float v = tile[w][d];
        float x = lat[base + (size_t)d * HW + w];
        out[base + (size_t)d * HW + w] = v;
        float df = v - x;
        lsum = fmaf(df, df, lsum);
    }
    __shared__ float red[256];
    red[t] = lsum;
    __syncthreads();
    for (int st = 128; st > 0; st >>= 1) {
        if (t < st) red[t] += red[t + st];
        __syncthreads();
    }
    if (t == 0) g_part[bh] = red[0];
}

// ---------------------------------------------------------------- kernel 8: final loss
__global__ void loss_kernel(float* __restrict__ out_loss) {
    __shared__ float red[1024];
    int t = threadIdx.x;
    red[t] = g_part[t];
    __syncthreads();
    for (int st = 512; st > 0; st >>= 1) {
        if (t < st) red[t] += red[t + st];
        __syncthreads();
    }
    if (t == 0) out_loss[0] = 1.25f * (red[0] / 8388608.0f);
}

// ----------------------------------------------------------------
extern "C" void kernel_launch(void* const* d_in, const int* in_sizes, int n_in,
                              void* d_out, int out_size) {
    const float* lat = (const float*)d_in[0];
    const float* emb = (const float*)d_in[1];
    if (n_in >= 2 && in_sizes[0] == D_ * K_) {   // defensive size-based ident
        lat = (const float*)d_in[1];
        emb = (const float*)d_in[0];
    }
    float* out = (float*)d_out;

    enorm_kernel<<<K_ / 256, 256>>>(emb);
    latconv_kernel<<<dim3(HW / 32, D_ / 32, B_), dim3(32, 32)>>>(lat);
    embconv_kernel<<<(D_ * K_ / 4) / 256, 256>>>(emb);

    // vq_mma stays the 4th launch so ncu's skip window profiles it.
    cudaFuncSetAttribute(vq_mma_kernel,
                         cudaFuncAttributeMaxDynamicSharedMemorySize, SM_TOTAL);
    vq_mma_kernel<<<N_ / 128, 512, SM_TOTAL>>>();

    embT_kernel<<<dim3(K_ / 32, D_ / 32), dim3(32, 32)>>>(emb);
    rescore_kernel<<<N_ / 32, 256>>>(lat, out + IDX_OFF);
    gather_loss_kernel<<<B_ * 32, 256>>>(lat, out);
    loss_kernel<<<1, 1024>>>(out + LOSS_OFF);
}

// round 10
// speedup vs baseline: 1.0266x; 1.0266x over previous
#include <cuda_runtime.h>
#include <cuda_bf16.h>
#include <cstdint>
#include <float.h>

// ---------------------------------------------------------------- problem dims
#define B_  32
#define D_  256
#define K_  8192
#define HW  1024
#define N_  32768
#define OUT_ELEMS 8388608
#define LOSS_OFF  OUT_ELEMS
#define IDX_OFF   (OUT_ELEMS + 1)

// ---------------------------------------------------------------- GEMM tiling
#define NCHUNK 64                    // 64 chunks of 128 codes
#define AS_STRIDE 264                // bf16 elems per A smem row (256 + 8 pad)
#define BS_STRIDE 136                // bf16 elems per B smem row (128 + 8 pad)
#define SM_A 0
#define SM_B (128 * AS_STRIDE * 2)   // 67584
#define BUFB (256 * BS_STRIDE * 2)   // 69632
#define SM_TOTAL (SM_B + 2 * BUFB)   // 206848

// ---------------------------------------------------------------- scratch
__device__ __align__(16) float g_enorm[K_];
__device__ __align__(16) int   g_idx[N_];
__device__ __align__(16) float g_part[1024];
__device__ __align__(16) int   g_top4[N_ * 4];
__device__ __align__(16) __nv_bfloat16 g_latT[(size_t)N_ * D_];   // [n][d] row-major
__device__ __align__(16) __nv_bfloat16 g_embBf[(size_t)D_ * K_];  // [d][k] row-major
__device__ __align__(16) float g_embT[(size_t)K_ * D_];           // [k][d] fp32

// ---------------------------------------------------------------- helpers
__device__ __forceinline__ uint32_t smem_u32(const void* p) {
    return (uint32_t)__cvta_generic_to_shared(p);
}
__device__ __forceinline__ void cp_async16(uint32_t dst, const void* src) {
    asm volatile("cp.async.cg.shared.global [%0], [%1], 16;" :: "r"(dst), "l"(src));
}
__device__ __forceinline__ void ldsm_x4(uint32_t* r, uint32_t addr) {
    asm volatile("ldmatrix.sync.aligned.m8n8.x4.shared.b16 {%0,%1,%2,%3}, [%4];"
                 : "=r"(r[0]), "=r"(r[1]), "=r"(r[2]), "=r"(r[3]) : "r"(addr));
}
__device__ __forceinline__ void ldsm_x4_t(uint32_t* r, uint32_t addr) {
    asm volatile("ldmatrix.sync.aligned.m8n8.x4.trans.shared.b16 {%0,%1,%2,%3}, [%4];"
                 : "=r"(r[0]), "=r"(r[1]), "=r"(r[2]), "=r"(r[3]) : "r"(addr));
}
__device__ __forceinline__ void mma_bf16(float* c, const uint32_t* a, uint32_t b0, uint32_t b1) {
    asm volatile(
        "mma.sync.aligned.m16n8k16.row.col.f32.bf16.bf16.f32 "
        "{%0,%1,%2,%3}, {%4,%5,%6,%7}, {%8,%9}, {%0,%1,%2,%3};"
        : "+f"(c[0]), "+f"(c[1]), "+f"(c[2]), "+f"(c[3])
        : "r"(a[0]), "r"(a[1]), "r"(a[2]), "r"(a[3]), "r"(b0), "r"(b1));
}

// ---------------------------------------------------------------- kernel 1: enorm
__global__ void enorm_kernel(const float* __restrict__ emb) {
    int k = blockIdx.x * blockDim.x + threadIdx.x;
    float s = 0.f;
#pragma unroll 8
    for (int d = 0; d < D_; ++d) {
        float v = emb[(size_t)d * K_ + k];
        s = fmaf(v, v, s);
    }
    g_enorm[k] = s;
}

// ---------------------------------------------------------------- kernel 2: latents -> bf16 [n][d]
__global__ void latconv_kernel(const float* __restrict__ lat) {
    __shared__ float t[32][33];
    int b = blockIdx.z, hw0 = blockIdx.x * 32, d0 = blockIdx.y * 32;
    t[threadIdx.y][threadIdx.x] =
        lat[((size_t)b * D_ + d0 + threadIdx.y) * HW + hw0 + threadIdx.x];
    __syncthreads();
    g_latT[((size_t)(b * HW + hw0 + threadIdx.y)) * D_ + d0 + threadIdx.x] =
        __float2bfloat16(t[threadIdx.x][threadIdx.y]);
}

// ---------------------------------------------------------------- kernel 3: embeddings -> bf16 [d][k]
__global__ void embconv_kernel(const float* __restrict__ emb) {
    size_t i = (size_t)blockIdx.x * blockDim.x + threadIdx.x;   // over D_*K_/4
    float4 v = reinterpret_cast<const float4*>(emb)[i];
    __nv_bfloat162 lo = __floats2bfloat162_rn(v.x, v.y);
    __nv_bfloat162 hi = __floats2bfloat162_rn(v.z, v.w);
    uint2 pk;
    pk.x = *reinterpret_cast<uint32_t*>(&lo);
    pk.y = *reinterpret_cast<uint32_t*>(&hi);
    reinterpret_cast<uint2*>(g_embBf)[i] = pk;
}

// ---------------------------------------------------------------- kernel 4: embeddings -> fp32 [k][d] (rescore + gather)
__global__ void embT_kernel(const float* __restrict__ emb) {
    __shared__ float t[32][33];
    int kb = blockIdx.x * 32, db = blockIdx.y * 32;
    t[threadIdx.y][threadIdx.x] = emb[(size_t)(db + threadIdx.y) * K_ + kb + threadIdx.x];
    __syncthreads();
    g_embT[(size_t)(kb + threadIdx.y) * D_ + db + threadIdx.x] = t[threadIdx.x][threadIdx.y];
}

// ---------------------------------------------------------------- kernel 5 support
__device__ __forceinline__ void prefetch_B(uint32_t sb, int tid, int u, int buf) {
    const char* bt = (const char*)g_embBf + (size_t)u * 256;
    uint32_t bd = sb + SM_B + buf * BUFB;
#pragma unroll
    for (int j = 0; j < 16; ++j) {
        int i = j * 256 + tid;
        int r = i >> 4, s = i & 15;
        cp_async16(bd + r * (BS_STRIDE * 2) + s * 16,
                   bt + (size_t)r * (K_ * 2) + s * 16);
    }
    asm volatile("cp.async.commit_group;" ::: "memory");
}

// Branchless top-2 update. Strict '<' + ascending col processing order
// reproduces first-occurrence argmin semantics (same as previous rounds).
#define TOP2(rs, v, c)                                          \
    {                                                           \
        bool b0_ = (v) < sv0[rs];                               \
        bool b1_ = (v) < sv1[rs];                               \
        sv1[rs] = b0_ ? sv0[rs] : (b1_ ? (v) : sv1[rs]);        \
        si1[rs] = b0_ ? si0[rs] : (b1_ ? (c) : si1[rs]);        \
        sv0[rs] = b0_ ? (v) : sv0[rs];                          \
        si0[rs] = b0_ ? (c) : si0[rs];                          \
    }

// One chunk of MMAs into A, optionally interleaving the epilogue of the
// previous chunk (accumulators P, columns based at cb0_prev). The epilogue
// group for (mf,nf) = (ks&3, ks>>2) is issued right after k-step ks, so its
// ALU ops fill the issue slots left free while HMMAs occupy the tensor pipe.
template<bool EPI>
__device__ __forceinline__ void mma_chunk(
    float (&A)[4][4][4], float (&P)[4][4][4],
    uint32_t bbase, const uint32_t* a_addr, int cb0_prev,
    float* sv0, float* sv1, int* si0, int* si1)
{
#pragma unroll
    for (int mf = 0; mf < 4; ++mf)
#pragma unroll
        for (int nf = 0; nf < 4; ++nf)
#pragma unroll
            for (int q = 0; q < 4; ++q) A[mf][nf][q] = 0.f;

#pragma unroll
    for (int ks = 0; ks < 16; ++ks) {
        uint32_t ar[4][4];
#pragma unroll
        for (int mf = 0; mf < 4; ++mf) ldsm_x4(ar[mf], a_addr[mf] + ks * 32);
        uint32_t br[2][4];
#pragma unroll
        for (int p = 0; p < 2; ++p)
            ldsm_x4_t(br[p], bbase + ks * 16 * (BS_STRIDE * 2) + p * 32);
#pragma unroll
        for (int mf = 0; mf < 4; ++mf)
#pragma unroll
            for (int nf = 0; nf < 4; ++nf)
                mma_bf16(A[mf][nf], ar[mf],
                         br[nf >> 1][(nf & 1) * 2], br[nf >> 1][(nf & 1) * 2 + 1]);

        if (EPI) {
            const int mf = ks & 3, nf = ks >> 2;
            const int c0 = cb0_prev + nf * 8;
            float2 e = __ldg(reinterpret_cast<const float2*>(&g_enorm[c0]));
#pragma unroll
            for (int half = 0; half < 2; ++half) {
                const int rs = mf * 2 + half;
                float v0 = fmaf(-2.f, P[mf][nf][half * 2 + 0], e.x);
                float v1 = fmaf(-2.f, P[mf][nf][half * 2 + 1], e.y);
                TOP2(rs, v0, c0);
                TOP2(rs, v1, c0 + 1);
            }
        }
    }
}

// Standalone epilogue for the final chunk.
__device__ __forceinline__ void epi_chunk(
    float (&P)[4][4][4], int cb0,
    float* sv0, float* sv1, int* si0, int* si1)
{
#pragma unroll
    for (int nf = 0; nf < 4; ++nf) {
        const int c0 = cb0 + nf * 8;
        float2 e = __ldg(reinterpret_cast<const float2*>(&g_enorm[c0]));
#pragma unroll
        for (int mf = 0; mf < 4; ++mf)
#pragma unroll
            for (int half = 0; half < 2; ++half) {
                const int rs = mf * 2 + half;
                float v0 = fmaf(-2.f, P[mf][nf][half * 2 + 0], e.x);
                float v1 = fmaf(-2.f, P[mf][nf][half * 2 + 1], e.y);
                TOP2(rs, v0, c0);
                TOP2(rs, v1, c0 + 1);
            }
    }
}

// ---------------------------------------------------------------- kernel 5: bf16 mma.sync GEMM + per-row candidates
// 256 threads, 8 warps 2(M)x4(N), warp tile 64x32. Double accumulators:
// chunk u's argmin epilogue executes inside chunk u+1's MMA issue window.
__global__ __launch_bounds__(256, 1)
void vq_mma_kernel() {
    extern __shared__ char smem[];
    const uint32_t sb = smem_u32(smem);
    const int tid = threadIdx.x, lane = tid & 31, wid = tid >> 5;
    const int wm = wid & 1;        // 0-1: 64-row half
    const int wn = wid >> 1;       // 0-3: 32-col quarter

    // preload A tile + B chunk 0 (group 0), then B chunk 1 (group 1)
    {
        const char* at = (const char*)(g_latT + (size_t)blockIdx.x * 128 * D_);
#pragma unroll
        for (int j = 0; j < 16; ++j) {
            int i = j * 256 + tid;
            int r = i >> 5, s = i & 31;
            cp_async16(sb + SM_A + r * (AS_STRIDE * 2) + s * 16, at + r * 512 + s * 16);
        }
    }
    prefetch_B(sb, tid, 0, 0);     // commits group with A included
    prefetch_B(sb, tid, 1, 1);

    uint32_t a_addr[4];
#pragma unroll
    for (int mf = 0; mf < 4; ++mf)
        a_addr[mf] = sb + SM_A + (wm * 64 + mf * 16 + (lane & 15)) * (AS_STRIDE * 2)
                   + (lane >> 4) * 16;
    const uint32_t b_off = (((lane >> 3) & 1) * 8 + (lane & 7)) * (BS_STRIDE * 2)
                         + (wn * 32 + (lane >> 4) * 8) * 2;
    const int cb_lane = wn * 32 + (lane & 3) * 2;

    float sv0[8], sv1[8];
    int   si0[8], si1[8];
#pragma unroll
    for (int r = 0; r < 8; ++r) { sv0[r] = sv1[r] = FLT_MAX; si0[r] = si1[r] = 0; }

    float accA[4][4][4], accB[4][4][4];

    asm volatile("cp.async.wait_group 1;" ::: "memory");   // A + B0 ready
    __syncthreads();

    // chunk 0 -> accA (no epilogue yet)
    mma_chunk<false>(accA, accA, sb + SM_B + 0 * BUFB + b_off, a_addr, 0,
                     sv0, sv1, si0, si1);

    // main loop, 2 chunks per iteration so acc/buffer parity is compile-time
    for (int u = 0; u < 62; u += 2) {
        // step 1: epi(u, accA) + MMA(u+1 -> accB), prefetch u+2 into buf0
        __syncthreads();
        prefetch_B(sb, tid, u + 2, 0);
        asm volatile("cp.async.wait_group 1;" ::: "memory");   // B(u+1) ready
        mma_chunk<true>(accB, accA, sb + SM_B + 1 * BUFB + b_off, a_addr,
                        (u << 7) + cb_lane, sv0, sv1, si0, si1);

        // step 2: epi(u+1, accB) + MMA(u+2 -> accA), prefetch u+3 into buf1
        __syncthreads();
        if (u + 3 < NCHUNK) {
            prefetch_B(sb, tid, u + 3, 1);
            asm volatile("cp.async.wait_group 1;" ::: "memory");  // B(u+2) ready
        } else {
            asm volatile("cp.async.wait_group 0;" ::: "memory");
        }
        mma_chunk<true>(accA, accB, sb + SM_B + 0 * BUFB + b_off, a_addr,
                        ((u + 1) << 7) + cb_lane, sv0, sv1, si0, si1);
    }

    // tail: epi(62, accA) + MMA(63 -> accB), then epi(63, accB)
    __syncthreads();
    asm volatile("cp.async.wait_group 0;" ::: "memory");       // B63 ready
    mma_chunk<true>(accB, accA, sb + SM_B + 1 * BUFB + b_off, a_addr,
                    (62 << 7) + cb_lane, sv0, sv1, si0, si1);
    epi_chunk(accB, (63 << 7) + cb_lane, sv0, sv1, si0, si1);

    // merge: 16 subsets x top-2 = 32 candidates per row -> top-4
    struct Pair { float v; int i; };
    Pair* pr = reinterpret_cast<Pair*>(smem);   // [128][32], 32KB (A region, done)
    __syncthreads();
#pragma unroll
    for (int rs = 0; rs < 8; ++rs) {
        int r = wm * 64 + (rs >> 1) * 16 + (lane >> 2) + (rs & 1) * 8;
        int sub = wn * 4 + (lane & 3);
        pr[r * 32 + sub * 2 + 0] = { sv0[rs], si0[rs] };
        pr[r * 32 + sub * 2 + 1] = { sv1[rs], si1[rs] };
    }
    __syncthreads();
    if (tid < 128) {
        float bv[4] = {FLT_MAX, FLT_MAX, FLT_MAX, FLT_MAX};
        int   bi[4] = {0x7fffffff, 0x7fffffff, 0x7fffffff, 0x7fffffff};
        for (int j = 0; j < 32; ++j) {
            float v = pr[tid * 32 + j].v;
            int   i = pr[tid * 32 + j].i;
            if (v < bv[3] || (v == bv[3] && i < bi[3])) {
                if (v < bv[0] || (v == bv[0] && i < bi[0])) {
                    bv[3]=bv[2]; bi[3]=bi[2]; bv[2]=bv[1]; bi[2]=bi[1];
                    bv[1]=bv[0]; bi[1]=bi[0]; bv[0]=v; bi[0]=i;
                } else if (v < bv[1] || (v == bv[1] && i < bi[1])) {
                    bv[3]=bv[2]; bi[3]=bi[2]; bv[2]=bv[1]; bi[2]=bi[1];
                    bv[1]=v; bi[1]=i;
                } else if (v < bv[2] || (v == bv[2] && i < bi[2])) {
                    bv[3]=bv[2]; bi[3]=bi[2]; bv[2]=v; bi[2]=i;
                } else {
                    bv[3]=v; bi[3]=i;
                }
            }
        }
        int row = blockIdx.x * 128 + tid;
#pragma unroll
        for (int s = 0; s < 4; ++s) g_top4[row * 4 + s] = bi[s];
    }
}

// ---------------------------------------------------------------- kernel 6: exact fp32 rescore of top-4
__global__ __launch_bounds__(256)
void rescore_kernel(const float* __restrict__ lat, float* __restrict__ out_idx_f) {
    int row = blockIdx.x * 32 + (threadIdx.x >> 3);
    int l8  = threadIdx.x & 7;
    int b = row >> 10, hw = row & (HW - 1);
    const float* z = lat + (size_t)b * (D_ * HW) + hw;
    int cand[4];
#pragma unroll
    for (int c = 0; c < 4; ++c) cand[c] = g_top4[row * 4 + c];
    float dot[4] = {0.f, 0.f, 0.f, 0.f};
    for (int d = l8; d < D_; d += 8) {
        float zv = z[(size_t)d * HW];
#pragma unroll
        for (int c = 0; c < 4; ++c)
            dot[c] = fmaf(zv, g_embT[(size_t)cand[c] * D_ + d], dot[c]);
    }
#pragma unroll
    for (int c = 0; c < 4; ++c) {
#pragma unroll
        for (int off = 4; off > 0; off >>= 1)
            dot[c] += __shfl_down_sync(0xffffffffu, dot[c], off, 8);
    }
    if (l8 == 0) {
        float bv = FLT_MAX; int bi = 0x7fffffff;
#pragma unroll
        for (int c = 0; c < 4; ++c) {
            float dist = fmaf(-2.f, dot[c], g_enorm[cand[c]]);
            if (dist < bv || (dist == bv && cand[c] < bi)) { bv = dist; bi = cand[c]; }
        }
        g_idx[row] = bi;
        out_idx_f[row] = (float)bi;
    }
}

// ---------------------------------------------------------------- kernel 7: gather + loss, fully coalesced via embT + smem transpose
__global__ __launch_bounds__(256)
void gather_loss_kernel(const float* __restrict__ lat, float* __restrict__ out) {
    __shared__ float tile[32][257];   // [w][d], padded: stride 257 mod 32 = 1
    int bh = blockIdx.x;              // (b,h)
    int b = bh >> 5, h = bh & 31;
    int t = threadIdx.x;

#pragma unroll 4
    for (int i = 0; i < 32; ++i) {
        int idx = g_idx[bh * 32 + i];
        tile[i][t] = g_embT[(size_t)idx * D_ + t];
    }
    __syncthreads();

    size_t base = (size_t)b * (D_ * HW) + h * 32;
    int w = t & 31, d0 = t >> 5;
    float lsum = 0.f;
#pragma unroll 4
    for (int i = 0; i < 32; ++i) {
        int d = i * 8 + d0;
        float v = tile[w][d];
        float x = lat[base + (size_t)d * HW + w];
        out[base + (size_t)d * HW + w] = v;
        float df = v - x;
        lsum = fmaf(df, df, lsum);
    }
    __shared__ float red[256];
    red[t] = lsum;
    __syncthreads();
    for (int st = 128; st > 0; st >>= 1) {
        if (t < st) red[t] += red[t + st];
        __syncthreads();
    }
    if (t == 0) g_part[bh] = red[0];
}

// ---------------------------------------------------------------- kernel 8: final loss
__global__ void loss_kernel(float* __restrict__ out_loss) {
    __shared__ float red[1024];
    int t = threadIdx.x;
    red[t] = g_part[t];
    __syncthreads();
    for (int st = 512; st > 0; st >>= 1) {
        if (t < st) red[t] += red[t + st];
        __syncthreads();
    }
    if (t == 0) out_loss[0] = 1.25f * (red[0] / 8388608.0f);
}

// ----------------------------------------------------------------
extern "C" void kernel_launch(void* const* d_in, const int* in_sizes, int n_in,
                              void* d_out, int out_size) {
    const float* lat = (const float*)d_in[0];
    const float* emb = (const float*)d_in[1];
    if (n_in >= 2 && in_sizes[0] == D_ * K_) {   // defensive size-based ident
        lat = (const float*)d_in[1];
        emb = (const float*)d_in[0];
    }
    float* out = (float*)d_out;

    enorm_kernel<<<K_ / 256, 256>>>(emb);
    latconv_kernel<<<dim3(HW / 32, D_ / 32, B_), dim3(32, 32)>>>(lat);
    embconv_kernel<<<(D_ * K_ / 4) / 256, 256>>>(emb);

    // vq_mma stays the 4th launch so ncu's skip window profiles it.
    cudaFuncSetAttribute(vq_mma_kernel,
                         cudaFuncAttributeMaxDynamicSharedMemorySize, SM_TOTAL);
    vq_mma_kernel<<<N_ / 128, 256, SM_TOTAL>>>();

    embT_kernel<<<dim3(K_ / 32, D_ / 32), dim3(32, 32)>>>(emb);
    rescore_kernel<<<N_ / 32, 256>>>(lat, out + IDX_OFF);
    gather_loss_kernel<<<B_ * 32, 256>>>(lat, out);
    loss_kernel<<<1, 1024>>>(out + LOSS_OFF);
}

// round 11
// speedup vs baseline: 1.0631x; 1.0356x over previous
#include <cuda_runtime.h>
#include <cuda_bf16.h>
#include <cstdint>
#include <float.h>

// ---------------------------------------------------------------- problem dims
#define B_  32
#define D_  256
#define K_  8192
#define HW  1024
#define N_  32768
#define OUT_ELEMS 8388608
#define LOSS_OFF  OUT_ELEMS
#define IDX_OFF   (OUT_ELEMS + 1)

// ---------------------------------------------------------------- GEMM tiling
#define NCHUNK 64                    // 64 chunks of 128 codes
#define AS_STRIDE 264                // bf16 elems per A smem row (256 + 8 pad)
#define BS_STRIDE 136                // bf16 elems per B smem row (128 + 8 pad)
#define SM_A 0
#define SM_B (128 * AS_STRIDE * 2)   // 67584
#define BUFB (256 * BS_STRIDE * 2)   // 69632
#define SM_TOTAL (SM_B + 2 * BUFB)   // 206848

#define EBIAS 1024.0f                // makes all scores positive (monotone bits)

// ---------------------------------------------------------------- scratch
__device__ __align__(16) float g_enorm[K_];                       // ||e||^2 + EBIAS
__device__ __align__(16) int   g_idx[N_];
__device__ __align__(16) float g_part[1024];
__device__ __align__(16) int   g_top4[N_ * 4];
__device__ __align__(16) __nv_bfloat16 g_latT[(size_t)N_ * D_];   // [n][d] bf16
__device__ __align__(16) float g_latF[(size_t)N_ * D_];           // [n][d] fp32
__device__ __align__(16) __nv_bfloat16 g_embBf[(size_t)D_ * K_];  // [d][k] bf16
__device__ __align__(16) float g_embT[(size_t)K_ * D_];           // [k][d] fp32

// ---------------------------------------------------------------- helpers
__device__ __forceinline__ uint32_t smem_u32(const void* p) {
    return (uint32_t)__cvta_generic_to_shared(p);
}
__device__ __forceinline__ void cp_async16(uint32_t dst, const void* src) {
    asm volatile("cp.async.cg.shared.global [%0], [%1], 16;" :: "r"(dst), "l"(src));
}
__device__ __forceinline__ void ldsm_x4(uint32_t* r, uint32_t addr) {
    asm volatile("ldmatrix.sync.aligned.m8n8.x4.shared.b16 {%0,%1,%2,%3}, [%4];"
                 : "=r"(r[0]), "=r"(r[1]), "=r"(r[2]), "=r"(r[3]) : "r"(addr));
}
__device__ __forceinline__ void ldsm_x4_t(uint32_t* r, uint32_t addr) {
    asm volatile("ldmatrix.sync.aligned.m8n8.x4.trans.shared.b16 {%0,%1,%2,%3}, [%4];"
                 : "=r"(r[0]), "=r"(r[1]), "=r"(r[2]), "=r"(r[3]) : "r"(addr));
}
__device__ __forceinline__ void mma_bf16(float* c, const uint32_t* a, uint32_t b0, uint32_t b1) {
    asm volatile(
        "mma.sync.aligned.m16n8k16.row.col.f32.bf16.bf16.f32 "
        "{%0,%1,%2,%3}, {%4,%5,%6,%7}, {%8,%9}, {%0,%1,%2,%3};"
        : "+f"(c[0]), "+f"(c[1]), "+f"(c[2]), "+f"(c[3])
        : "r"(a[0]), "r"(a[1]), "r"(a[2]), "r"(a[3]), "r"(b0), "r"(b1));
}

// ---------------------------------------------------------------- kernel 1: enorm (biased)
__global__ void enorm_kernel(const float* __restrict__ emb) {
    int k = blockIdx.x * blockDim.x + threadIdx.x;
    float s = 0.f;
#pragma unroll 8
    for (int d = 0; d < D_; ++d) {
        float v = emb[(size_t)d * K_ + k];
        s = fmaf(v, v, s);
    }
    g_enorm[k] = s + EBIAS;   // bias is a per-row constant in the score: argmin invariant
}

// ---------------------------------------------------------------- kernel 2: latents -> bf16 + fp32 [n][d]
__global__ void latconv_kernel(const float* __restrict__ lat) {
    __shared__ float t[32][33];
    int b = blockIdx.z, hw0 = blockIdx.x * 32, d0 = blockIdx.y * 32;
    t[threadIdx.y][threadIdx.x] =
        lat[((size_t)b * D_ + d0 + threadIdx.y) * HW + hw0 + threadIdx.x];
    __syncthreads();
    float v = t[threadIdx.x][threadIdx.y];
    size_t o = ((size_t)(b * HW + hw0 + threadIdx.y)) * D_ + d0 + threadIdx.x;
    g_latT[o] = __float2bfloat16(v);
    g_latF[o] = v;
}

// ---------------------------------------------------------------- kernel 3: embeddings -> bf16 [d][k]
__global__ void embconv_kernel(const float* __restrict__ emb) {
    size_t i = (size_t)blockIdx.x * blockDim.x + threadIdx.x;   // over D_*K_/4
    float4 v = reinterpret_cast<const float4*>(emb)[i];
    __nv_bfloat162 lo = __floats2bfloat162_rn(v.x, v.y);
    __nv_bfloat162 hi = __floats2bfloat162_rn(v.z, v.w);
    uint2 pk;
    pk.x = *reinterpret_cast<uint32_t*>(&lo);
    pk.y = *reinterpret_cast<uint32_t*>(&hi);
    reinterpret_cast<uint2*>(g_embBf)[i] = pk;
}

// ---------------------------------------------------------------- kernel 4: embeddings -> fp32 [k][d]
__global__ void embT_kernel(const float* __restrict__ emb) {
    __shared__ float t[32][33];
    int kb = blockIdx.x * 32, db = blockIdx.y * 32;
    t[threadIdx.y][threadIdx.x] = emb[(size_t)(db + threadIdx.y) * K_ + kb + threadIdx.x];
    __syncthreads();
    g_embT[(size_t)(kb + threadIdx.y) * D_ + db + threadIdx.x] = t[threadIdx.x][threadIdx.y];
}

// ---------------------------------------------------------------- kernel 5 support
__device__ __forceinline__ void prefetch_B(uint32_t sb, int tid, int u, int buf) {
    const char* bt = (const char*)g_embBf + (size_t)u * 256;
    uint32_t bd = sb + SM_B + buf * BUFB;
#pragma unroll
    for (int j = 0; j < 16; ++j) {
        int i = j * 256 + tid;
        int r = i >> 4, s = i & 15;
        cp_async16(bd + r * (BS_STRIDE * 2) + s * 16,
                   bt + (size_t)r * (K_ * 2) + s * 16);
    }
    asm volatile("cp.async.commit_group;" ::: "memory");
}

// Packed top-2: pv carries truncated positive score bits | 9-bit local id.
// umin/umax only; ties (equal truncated score) -> smaller id = earlier column.
#define TOP2P(rs, scf, c9)                                          \
    {                                                               \
        uint32_t pv_ = (__float_as_uint(scf) & 0xFFFFFE00u) | (c9); \
        uint32_t mx_ = p0[rs] > pv_ ? p0[rs] : pv_;                 \
        p1[rs] = p1[rs] < mx_ ? p1[rs] : mx_;                       \
        p0[rs] = p0[rs] < pv_ ? p0[rs] : pv_;                       \
    }

// One chunk of MMAs into A; optionally interleave the previous chunk's
// epilogue (accumulators P). Epilogue group (mf,nf)=(ks&3,ks>>2) issues right
// after k-step ks so its ALU ops ride in HMMA shadow.
template<bool EPI>
__device__ __forceinline__ void mma_chunk(
    float (&A)[4][4][4], float (&P)[4][4][4],
    uint32_t bbase, const uint32_t* a_addr,
    int cb0_prev, uint32_t u9_prev,
    uint32_t* p0, uint32_t* p1)
{
#pragma unroll
    for (int mf = 0; mf < 4; ++mf)
#pragma unroll
        for (int nf = 0; nf < 4; ++nf)
#pragma unroll
            for (int q = 0; q < 4; ++q) A[mf][nf][q] = 0.f;

#pragma unroll
    for (int ks = 0; ks < 16; ++ks) {
        uint32_t ar[4][4];
#pragma unroll
        for (int mf = 0; mf < 4; ++mf) ldsm_x4(ar[mf], a_addr[mf] + ks * 32);
        uint32_t br[2][4];
#pragma unroll
        for (int p = 0; p < 2; ++p)
            ldsm_x4_t(br[p], bbase + ks * 16 * (BS_STRIDE * 2) + p * 32);
#pragma unroll
        for (int mf = 0; mf < 4; ++mf)
#pragma unroll
            for (int nf = 0; nf < 4; ++nf)
                mma_bf16(A[mf][nf], ar[mf],
                         br[nf >> 1][(nf & 1) * 2], br[nf >> 1][(nf & 1) * 2 + 1]);

        if (EPI) {
            const int mf = ks & 3, nf = ks >> 2;
            const int c0 = cb0_prev + nf * 8;
            const uint32_t c9 = u9_prev + nf * 2;
            float2 e = __ldg(reinterpret_cast<const float2*>(&g_enorm[c0]));
#pragma unroll
            for (int half = 0; half < 2; ++half) {
                const int rs = mf * 2 + half;
                float s0 = fmaf(-2.f, P[mf][nf][half * 2 + 0], e.x);
                float s1 = fmaf(-2.f, P[mf][nf][half * 2 + 1], e.y);
                TOP2P(rs, s0, c9);
                TOP2P(rs, s1, c9 + 1);
            }
        }
    }
}

__device__ __forceinline__ void epi_chunk(
    float (&P)[4][4][4], int cb0, uint32_t u9,
    uint32_t* p0, uint32_t* p1)
{
#pragma unroll
    for (int nf = 0; nf < 4; ++nf) {
        const int c0 = cb0 + nf * 8;
        const uint32_t c9 = u9 + nf * 2;
        float2 e = __ldg(reinterpret_cast<const float2*>(&g_enorm[c0]));
#pragma unroll
        for (int mf = 0; mf < 4; ++mf)
#pragma unroll
            for (int half = 0; half < 2; ++half) {
                const int rs = mf * 2 + half;
                float s0 = fmaf(-2.f, P[mf][nf][half * 2 + 0], e.x);
                float s1 = fmaf(-2.f, P[mf][nf][half * 2 + 1], e.y);
                TOP2P(rs, s0, c9);
                TOP2P(rs, s1, c9 + 1);
            }
    }
}

// decode 9-bit local id (u<<3 | nf*2+q) back to a global column
__device__ __forceinline__ int dec9(uint32_t p, int wn, int l3) {
    int loc = p & 0x1FF;
    int u = loc >> 3, jj = loc & 7;
    return u * 128 + wn * 32 + l3 * 2 + (jj >> 1) * 8 + (jj & 1);
}

// ---------------------------------------------------------------- kernel 5: bf16 mma.sync GEMM + packed top-2
__global__ __launch_bounds__(256, 1)
void vq_mma_kernel() {
    extern __shared__ char smem[];
    const uint32_t sb = smem_u32(smem);
    const int tid = threadIdx.x, lane = tid & 31, wid = tid >> 5;
    const int wm = wid & 1;        // 0-1: 64-row half
    const int wn = wid >> 1;       // 0-3: 32-col quarter

    {
        const char* at = (const char*)(g_latT + (size_t)blockIdx.x * 128 * D_);
#pragma unroll
        for (int j = 0; j < 16; ++j) {
            int i = j * 256 + tid;
            int r = i >> 5, s = i & 31;
            cp_async16(sb + SM_A + r * (AS_STRIDE * 2) + s * 16, at + r * 512 + s * 16);
        }
    }
    prefetch_B(sb, tid, 0, 0);
    prefetch_B(sb, tid, 1, 1);

    uint32_t a_addr[4];
#pragma unroll
    for (int mf = 0; mf < 4; ++mf)
        a_addr[mf] = sb + SM_A + (wm * 64 + mf * 16 + (lane & 15)) * (AS_STRIDE * 2)
                   + (lane >> 4) * 16;
    const uint32_t b_off = (((lane >> 3) & 1) * 8 + (lane & 7)) * (BS_STRIDE * 2)
                         + (wn * 32 + (lane >> 4) * 8) * 2;
    const int cb_lane = wn * 32 + (lane & 3) * 2;

    uint32_t p0[8], p1[8];
#pragma unroll
    for (int r = 0; r < 8; ++r) { p0[r] = 0xFFFFFFFFu; p1[r] = 0xFFFFFFFFu; }

    float accA[4][4][4], accB[4][4][4];

    asm volatile("cp.async.wait_group 1;" ::: "memory");   // A + B0 ready
    __syncthreads();

    mma_chunk<false>(accA, accA, sb + SM_B + 0 * BUFB + b_off, a_addr, 0, 0, p0, p1);

    for (int u = 0; u < 62; u += 2) {
        __syncthreads();
        prefetch_B(sb, tid, u + 2, 0);
        asm volatile("cp.async.wait_group 1;" ::: "memory");   // B(u+1) ready
        mma_chunk<true>(accB, accA, sb + SM_B + 1 * BUFB + b_off, a_addr,
                        (u << 7) + cb_lane, (uint32_t)(u << 3), p0, p1);

        __syncthreads();
        if (u + 3 < NCHUNK) {
            prefetch_B(sb, tid, u + 3, 1);
            asm volatile("cp.async.wait_group 1;" ::: "memory");  // B(u+2) ready
        } else {
            asm volatile("cp.async.wait_group 0;" ::: "memory");
        }
        mma_chunk<true>(accA, accB, sb + SM_B + 0 * BUFB + b_off, a_addr,
                        ((u + 1) << 7) + cb_lane, (uint32_t)((u + 1) << 3), p0, p1);
    }

    __syncthreads();
    asm volatile("cp.async.wait_group 0;" ::: "memory");       // B63 ready
    mma_chunk<true>(accB, accA, sb + SM_B + 1 * BUFB + b_off, a_addr,
                    (62 << 7) + cb_lane, (uint32_t)(62 << 3), p0, p1);
    epi_chunk(accB, (63 << 7) + cb_lane, (uint32_t)(63 << 3), p0, p1);

    // merge: 16 subsets x top-2 -> top-4 per row. Store truncated score bits
    // (uint, monotone) + decoded global index; lexicographic min = jax ties.
    struct Pair { uint32_t v; int i; };
    Pair* pr = reinterpret_cast<Pair*>(smem);   // [128][32], 32KB (A region, done)
    const int l3 = lane & 3;
    __syncthreads();
#pragma unroll
    for (int rs = 0; rs < 8; ++rs) {
        int r = wm * 64 + (rs >> 1) * 16 + (lane >> 2) + (rs & 1) * 8;
        int sub = wn * 4 + l3;
        pr[r * 32 + sub * 2 + 0] = { p0[rs] & 0xFFFFFE00u, dec9(p0[rs], wn, l3) };
        pr[r * 32 + sub * 2 + 1] = { p1[rs] & 0xFFFFFE00u, dec9(p1[rs], wn, l3) };
    }
    __syncthreads();
    if (tid < 128) {
        uint32_t bv[4] = {0xFFFFFFFFu, 0xFFFFFFFFu, 0xFFFFFFFFu, 0xFFFFFFFFu};
        int      bi[4] = {0x7fffffff, 0x7fffffff, 0x7fffffff, 0x7fffffff};
        for (int j = 0; j < 32; ++j) {
            uint32_t v = pr[tid * 32 + j].v;
            int      i = pr[tid * 32 + j].i;
            if (v < bv[3] || (v == bv[3] && i < bi[3])) {
                if (v < bv[0] || (v == bv[0] && i < bi[0])) {
                    bv[3]=bv[2]; bi[3]=bi[2]; bv[2]=bv[1]; bi[2]=bi[1];
                    bv[1]=bv[0]; bi[1]=bi[0]; bv[0]=v; bi[0]=i;
                } else if (v < bv[1] || (v == bv[1] && i < bi[1])) {
                    bv[3]=bv[2]; bi[3]=bi[2]; bv[2]=bv[1]; bi[2]=bi[1];
                    bv[1]=v; bi[1]=i;
                } else if (v < bv[2] || (v == bv[2] && i < bi[2])) {
                    bv[3]=bv[2]; bi[3]=bi[2]; bv[2]=v; bi[2]=i;
                } else {
                    bv[3]=v; bi[3]=i;
                }
            }
        }
        int row = blockIdx.x * 128 + tid;
#pragma unroll
        for (int s = 0; s < 4; ++s) g_top4[row * 4 + s] = bi[s];
    }
}

// ---------------------------------------------------------------- kernel 6: fused exact rescore + gather + loss partials
// Block = one (b,h): 32 rows. Phase 1: exact fp32 rescore of top-4 using a
// coalesced smem z-tile. Phase 2: gather output + squared-error partials.
#define SMF_Z 0
#define SMF_E (32 * 257)
#define SMF_TOTAL ((2 * 32 * 257 + 32 + 256) * 4)
__global__ __launch_bounds__(256)
void rescore_gather_kernel(float* __restrict__ out, float* __restrict__ out_idx_f) {
    extern __shared__ float sm[];
    float* zt = sm + SMF_Z;            // [32][257] fp32 latents (row-major)
    float* et = sm + SMF_E;            // [32][257] gathered embeddings
    int*   sidx = (int*)(sm + 2 * 32 * 257);
    float* red  = sm + 2 * 32 * 257 + 32;

    int bh = blockIdx.x;               // (b,h)
    int b = bh >> 5, h = bh & 31;
    int t = threadIdx.x;

    // load z tile: 32 rows x 256 d, coalesced over d
#pragma unroll 4
    for (int i = 0; i < 32; ++i)
        zt[i * 257 + t] = g_latF[(size_t)(bh * 32 + i) * D_ + t];
    __syncthreads();

    // phase 1: rescore — 8 threads per row
    {
        int rl = t >> 3, l8 = t & 7;
        int row = bh * 32 + rl;
        int cand[4];
#pragma unroll
        for (int c = 0; c < 4; ++c) cand[c] = g_top4[row * 4 + c];
        float dot[4] = {0.f, 0.f, 0.f, 0.f};
        for (int d = l8; d < D_; d += 8) {
            float zv = zt[rl * 257 + d];
#pragma unroll
            for (int c = 0; c < 4; ++c)
                dot[c] = fmaf(zv, g_embT[(size_t)cand[c] * D_ + d], dot[c]);
        }
#pragma unroll
        for (int c = 0; c < 4; ++c) {
#pragma unroll
            for (int off = 4; off > 0; off >>= 1)
                dot[c] += __shfl_down_sync(0xffffffffu, dot[c], off, 8);
        }
        if (l8 == 0) {
            float bv = FLT_MAX; int bi = 0x7fffffff;
#pragma unroll
            for (int c = 0; c < 4; ++c) {
                // biased enorm: constant offset per row, argmin invariant
                float dist = fmaf(-2.f, dot[c], g_enorm[cand[c]]);
                if (dist < bv || (dist == bv && cand[c] < bi)) { bv = dist; bi = cand[c]; }
            }
            g_idx[row] = bi;
            sidx[rl] = bi;
            out_idx_f[row] = (float)bi;
        }
    }
    __syncthreads();

    // load gathered embedding rows (coalesced over d)
#pragma unroll 4
    for (int i = 0; i < 32; ++i)
        et[i * 257 + t] = g_embT[(size_t)sidx[i] * D_ + t];
    __syncthreads();

    // phase 2: write output coalesced over w; fused loss partials
    size_t base = (size_t)b * (D_ * HW) + h * 32;
    int w = t & 31, d0 = t >> 5;
    float lsum = 0.f;
#pragma unroll 4
    for (int i = 0; i < 32; ++i) {
        int d = i * 8 + d0;
        float v = et[w * 257 + d];
        float x = zt[w * 257 + d];
        out[base + (size_t)d * HW + w] = v;
        float df = v - x;
        lsum = fmaf(df, df, lsum);
    }
    red[t] = lsum;
    __syncthreads();
    for (int st = 128; st > 0; st >>= 1) {
        if (t < st) red[t] += red[t + st];
        __syncthreads();
    }
    if (t == 0) g_part[bh] = red[0];
}

// ---------------------------------------------------------------- kernel 7: final loss
__global__ void loss_kernel(float* __restrict__ out_loss) {
    __shared__ float red[1024];
    int t = threadIdx.x;
    red[t] = g_part[t];
    __syncthreads();
    for (int st = 512; st > 0; st >>= 1) {
        if (t < st) red[t] += red[t + st];
        __syncthreads();
    }
    if (t == 0) out_loss[0] = 1.25f * (red[0] / 8388608.0f);
}

// ----------------------------------------------------------------
extern "C" void kernel_launch(void* const* d_in, const int* in_sizes, int n_in,
                              void* d_out, int out_size) {
    const float* lat = (const float*)d_in[0];
    const float* emb = (const float*)d_in[1];
    if (n_in >= 2 && in_sizes[0] == D_ * K_) {   // defensive size-based ident
        lat = (const float*)d_in[1];
        emb = (const float*)d_in[0];
    }
    float* out = (float*)d_out;

    enorm_kernel<<<K_ / 256, 256>>>(emb);
    latconv_kernel<<<dim3(HW / 32, D_ / 32, B_), dim3(32, 32)>>>(lat);
    embconv_kernel<<<(D_ * K_ / 4) / 256, 256>>>(emb);

    // vq_mma stays the 4th launch so ncu's skip window profiles it.
    cudaFuncSetAttribute(vq_mma_kernel,
                         cudaFuncAttributeMaxDynamicSharedMemorySize, SM_TOTAL);
    vq_mma_kernel<<<N_ / 128, 256, SM_TOTAL>>>();

    embT_kernel<<<dim3(K_ / 32, D_ / 32), dim3(32, 32)>>>(emb);
    cudaFuncSetAttribute(rescore_gather_kernel,
                         cudaFuncAttributeMaxDynamicSharedMemorySize, SMF_TOTAL);
    rescore_gather_kernel<<<B_ * 32, 256, SMF_TOTAL>>>(out, out + IDX_OFF);
    loss_kernel<<<1, 1024>>>(out + LOSS_OFF);
}

// round 12
// speedup vs baseline: 1.1511x; 1.0827x over previous
#include <cuda_runtime.h>
#include <cuda_bf16.h>
#include <cstdint>
#include <float.h>

// ---------------------------------------------------------------- problem dims
#define B_  32
#define D_  256
#define K_  8192
#define HW  1024
#define N_  32768
#define OUT_ELEMS 8388608
#define LOSS_OFF  OUT_ELEMS
#define IDX_OFF   (OUT_ELEMS + 1)

// ---------------------------------------------------------------- GEMM tiling
#define NCHUNK 64                    // 64 chunks of 128 codes (32 per warp pair)
#define AS_STRIDE 264                // bf16 elems per A smem row (256 + 8 pad)
#define SL_STRIDE 80                 // bytes per B-slice row (64B data + 16 pad)
#define SLICE_BUF (256 * SL_STRIDE)  // 20480 bytes: one 256x32 bf16 slice
#define SM_A 0
#define SM_S (128 * AS_STRIDE * 2)   // 67584: B slices start here
#define SM_TOTAL (SM_S + 8 * SLICE_BUF)  // 231424 <= 232448

#define EBIAS 1024.0f                // keeps packed scores positive (monotone bits)

// ---------------------------------------------------------------- scratch
__device__ __align__(16) float g_enorm[K_];                       // ||e||^2 + EBIAS
__device__ __align__(16) int   g_idx[N_];
__device__ __align__(16) float g_part[1024];
__device__ __align__(16) int   g_top4[N_ * 4];
__device__ __align__(16) __nv_bfloat16 g_latT[(size_t)N_ * D_];   // [n][d] bf16
__device__ __align__(16) __nv_bfloat16 g_embBf[(size_t)D_ * K_];  // [d][k] bf16
__device__ __align__(16) float g_embT[(size_t)K_ * D_];           // [k][d] fp32

// ---------------------------------------------------------------- helpers
__device__ __forceinline__ uint32_t smem_u32(const void* p) {
    return (uint32_t)__cvta_generic_to_shared(p);
}
__device__ __forceinline__ void cp_async16(uint32_t dst, const void* src) {
    asm volatile("cp.async.cg.shared.global [%0], [%1], 16;" :: "r"(dst), "l"(src));
}
__device__ __forceinline__ void ldsm_x4(uint32_t* r, uint32_t addr) {
    asm volatile("ldmatrix.sync.aligned.m8n8.x4.shared.b16 {%0,%1,%2,%3}, [%4];"
                 : "=r"(r[0]), "=r"(r[1]), "=r"(r[2]), "=r"(r[3]) : "r"(addr));
}
__device__ __forceinline__ void ldsm_x4_t(uint32_t* r, uint32_t addr) {
    asm volatile("ldmatrix.sync.aligned.m8n8.x4.trans.shared.b16 {%0,%1,%2,%3}, [%4];"
                 : "=r"(r[0]), "=r"(r[1]), "=r"(r[2]), "=r"(r[3]) : "r"(addr));
}
__device__ __forceinline__ void mma_bf16(float* c, const uint32_t* a, uint32_t b0, uint32_t b1) {
    asm volatile(
        "mma.sync.aligned.m16n8k16.row.col.f32.bf16.bf16.f32 "
        "{%0,%1,%2,%3}, {%4,%5,%6,%7}, {%8,%9}, {%0,%1,%2,%3};"
        : "+f"(c[0]), "+f"(c[1]), "+f"(c[2]), "+f"(c[3])
        : "r"(a[0]), "r"(a[1]), "r"(a[2]), "r"(a[3]), "r"(b0), "r"(b1));
}
// pairwise named barrier: the two warps (wm=0,1) of column-group wn
#define PAIR_BAR(wn) \
    asm volatile("bar.sync %0, 64;" :: "r"(1 + (wn)) : "memory")

// ---------------------------------------------------------------- kernel 1: embconv + enorm fused (single pass over emb)
__global__ __launch_bounds__(256)
void embprep_kernel(const float* __restrict__ emb) {
    int k = blockIdx.x * 256 + threadIdx.x;
    float s = 0.f;
#pragma unroll 8
    for (int d = 0; d < D_; ++d) {
        float v = emb[(size_t)d * K_ + k];
        s = fmaf(v, v, s);
        g_embBf[(size_t)d * K_ + k] = __float2bfloat16(v);
    }
    g_enorm[k] = s + EBIAS;   // constant bias: argmin invariant
}

// ---------------------------------------------------------------- kernel 2: latents -> bf16 [n][d]
__global__ void latconv_kernel(const float* __restrict__ lat) {
    __shared__ float t[32][33];
    int b = blockIdx.z, hw0 = blockIdx.x * 32, d0 = blockIdx.y * 32;
    t[threadIdx.y][threadIdx.x] =
        lat[((size_t)b * D_ + d0 + threadIdx.y) * HW + hw0 + threadIdx.x];
    __syncthreads();
    g_latT[((size_t)(b * HW + hw0 + threadIdx.y)) * D_ + d0 + threadIdx.x] =
        __float2bfloat16(t[threadIdx.x][threadIdx.y]);
}

// ---------------------------------------------------------------- kernel 3: embeddings -> fp32 [k][d] (rescore + gather)
__global__ void embT_kernel(const float* __restrict__ emb) {
    __shared__ float t[32][33];
    int kb = blockIdx.x * 32, db = blockIdx.y * 32;
    t[threadIdx.y][threadIdx.x] = emb[(size_t)(db + threadIdx.y) * K_ + kb + threadIdx.x];
    __syncthreads();
    g_embT[(size_t)(kb + threadIdx.y) * D_ + db + threadIdx.x] = t[threadIdx.x][threadIdx.y];
}

// ---------------------------------------------------------------- kernel 4 support
// Per-pair B slice prefetch: this pair's 32 columns of chunk u. Warp wm copies
// rows [wm*128, wm*128+128). 16 x 16B per lane.
__device__ __forceinline__ void prefetch_slice(uint32_t bufaddr, int lane, int wm,
                                               int colbase_bytes) {
    const char* base = (const char*)g_embBf + colbase_bytes;
#pragma unroll
    for (int j = 0; j < 16; ++j) {
        int idx = j * 32 + lane;
        int r = idx >> 2, s = idx & 3;
        int row = wm * 128 + r;
        cp_async16(bufaddr + row * SL_STRIDE + s * 16,
                   base + (size_t)row * (K_ * 2) + s * 16);
    }
    asm volatile("cp.async.commit_group;" ::: "memory");
}

// Packed top-2: truncated positive score bits | 9-bit local id; umin/umax only.
#define TOP2P(rs, scf, c9)                                          \
    {                                                               \
        uint32_t pv_ = (__float_as_uint(scf) & 0xFFFFFE00u) | (c9); \
        uint32_t mx_ = p0[rs] > pv_ ? p0[rs] : pv_;                 \
        p1[rs] = p1[rs] < mx_ ? p1[rs] : mx_;                       \
        p0[rs] = p0[rs] < pv_ ? p0[rs] : pv_;                       \
    }

// One chunk of MMAs into A; optionally interleave prev chunk's epilogue (P).
template<bool EPI>
__device__ __forceinline__ void mma_chunk(
    float (&A)[4][4][4], float (&P)[4][4][4],
    uint32_t bbase, const uint32_t* a_addr,
    int cb0_prev, uint32_t u9_prev,
    uint32_t* p0, uint32_t* p1)
{
#pragma unroll
    for (int mf = 0; mf < 4; ++mf)
#pragma unroll
        for (int nf = 0; nf < 4; ++nf)
#pragma unroll
            for (int q = 0; q < 4; ++q) A[mf][nf][q] = 0.f;

#pragma unroll
    for (int ks = 0; ks < 16; ++ks) {
        uint32_t ar[4][4];
#pragma unroll
        for (int mf = 0; mf < 4; ++mf) ldsm_x4(ar[mf], a_addr[mf] + ks * 32);
        uint32_t br[2][4];
#pragma unroll
        for (int p = 0; p < 2; ++p)
            ldsm_x4_t(br[p], bbase + ks * 16 * SL_STRIDE + p * 32);
#pragma unroll
        for (int mf = 0; mf < 4; ++mf)
#pragma unroll
            for (int nf = 0; nf < 4; ++nf)
                mma_bf16(A[mf][nf], ar[mf],
                         br[nf >> 1][(nf & 1) * 2], br[nf >> 1][(nf & 1) * 2 + 1]);

        if (EPI) {
            const int mf = ks & 3, nf = ks >> 2;
            const int c0 = cb0_prev + nf * 8;
            const uint32_t c9 = u9_prev + nf * 2;
            float2 e = __ldg(reinterpret_cast<const float2*>(&g_enorm[c0]));
#pragma unroll
            for (int half = 0; half < 2; ++half) {
                const int rs = mf * 2 + half;
                float s0 = fmaf(-2.f, P[mf][nf][half * 2 + 0], e.x);
                float s1 = fmaf(-2.f, P[mf][nf][half * 2 + 1], e.y);
                TOP2P(rs, s0, c9);
                TOP2P(rs, s1, c9 + 1);
            }
        }
    }
}

__device__ __forceinline__ void epi_chunk(
    float (&P)[4][4][4], int cb0, uint32_t u9,
    uint32_t* p0, uint32_t* p1)
{
#pragma unroll
    for (int nf = 0; nf < 4; ++nf) {
        const int c0 = cb0 + nf * 8;
        const uint32_t c9 = u9 + nf * 2;
        float2 e = __ldg(reinterpret_cast<const float2*>(&g_enorm[c0]));
#pragma unroll
        for (int mf = 0; mf < 4; ++mf)
#pragma unroll
            for (int half = 0; half < 2; ++half) {
                const int rs = mf * 2 + half;
                float s0 = fmaf(-2.f, P[mf][nf][half * 2 + 0], e.x);
                float s1 = fmaf(-2.f, P[mf][nf][half * 2 + 1], e.y);
                TOP2P(rs, s0, c9);
                TOP2P(rs, s1, c9 + 1);
            }
    }
}

__device__ __forceinline__ int dec9(uint32_t p, int wn, int l3) {
    int loc = p & 0x1FF;
    int u = loc >> 3, jj = loc & 7;
    return u * 128 + wn * 32 + l3 * 2 + (jj >> 1) * 8 + (jj & 1);
}

// ---------------------------------------------------------------- kernel 4: bf16 mma.sync GEMM, pair-decoupled B pipeline
__global__ __launch_bounds__(256, 1)
void vq_mma_kernel() {
    extern __shared__ char smem[];
    const uint32_t sb = smem_u32(smem);
    const int tid = threadIdx.x, lane = tid & 31, wid = tid >> 5;
    const int wm = wid & 1;        // 0-1: 64-row half (M)
    const int wn = wid >> 1;       // 0-3: 32-col quarter (N) = pair id

    const uint32_t pair_base = sb + SM_S + wn * (2 * SLICE_BUF);
    const uint32_t buf0 = pair_base, buf1 = pair_base + SLICE_BUF;
    const int colw = wn * 64;      // this pair's column byte offset within a chunk

    // ---- prologue: A tile + slice(chunk0) in group0; slice(chunk1) in group1
    {
        const char* at = (const char*)(g_latT + (size_t)blockIdx.x * 128 * D_);
#pragma unroll
        for (int j = 0; j < 16; ++j) {
            int i = j * 256 + tid;
            int r = i >> 5, s = i & 31;
            cp_async16(sb + SM_A + r * (AS_STRIDE * 2) + s * 16, at + r * 512 + s * 16);
        }
    }
    prefetch_slice(buf0, lane, wm, 0 * 256 + colw);
    prefetch_slice(buf1, lane, wm, 1 * 256 + colw);

    uint32_t a_addr[4];
#pragma unroll
    for (int mf = 0; mf < 4; ++mf)
        a_addr[mf] = sb + SM_A + (wm * 64 + mf * 16 + (lane & 15)) * (AS_STRIDE * 2)
                   + (lane >> 4) * 16;
    // B ldsm offset inside slice: 16 k-rows x 16 cols per x4.trans
    const uint32_t b_off = ((((lane >> 3) & 1) * 8 + (lane & 7)) * SL_STRIDE)
                         + (lane >> 4) * 16;
    const int cb_lane = wn * 32 + (lane & 3) * 2;

    uint32_t p0[8], p1[8];
#pragma unroll
    for (int r = 0; r < 8; ++r) { p0[r] = 0xFFFFFFFFu; p1[r] = 0xFFFFFFFFu; }

    float accA[4][4][4], accB[4][4][4];

    asm volatile("cp.async.wait_group 1;" ::: "memory");   // A + slice0 landed (own)
    __syncthreads();                                       // everyone's A + slice0 visible

    // chunk 0 -> accA (no epilogue)
    mma_chunk<false>(accA, accA, buf0 + b_off, a_addr, 0, 0, p0, p1);

    // ---- pair-local pipeline: no block-wide syncs in the mainloop
    for (int u = 0; u < 62; u += 2) {
        PAIR_BAR(wn);                                       // both done reading buf0
        prefetch_slice(buf0, lane, wm, (u + 2) * 256 + colw);
        asm volatile("cp.async.wait_group 1;" ::: "memory"); // G(u+1) landed (own)
        PAIR_BAR(wn);                                       // partner's too
        mma_chunk<true>(accB, accA, buf1 + b_off, a_addr,
                        (u << 7) + cb_lane, (uint32_t)(u << 3), p0, p1);

        PAIR_BAR(wn);                                       // both done reading buf1
        prefetch_slice(buf1, lane, wm, (u + 3) * 256 + colw);
        asm volatile("cp.async.wait_group 1;" ::: "memory"); // G(u+2) landed (own)
        PAIR_BAR(wn);                                       // partner's too
        mma_chunk<true>(accA, accB, buf0 + b_off, a_addr,
                        ((u + 1) << 7) + cb_lane, (uint32_t)((u + 1) << 3), p0, p1);
    }

    PAIR_BAR(wn);
    asm volatile("cp.async.wait_group 0;" ::: "memory");    // G63 landed (own)
    PAIR_BAR(wn);                                           // partner's too
    mma_chunk<true>(accB, accA, buf1 + b_off, a_addr,
                    (62 << 7) + cb_lane, (uint32_t)(62 << 3), p0, p1);
    epi_chunk(accB, (63 << 7) + cb_lane, (uint32_t)(63 << 3), p0, p1);

    // ---- merge: 16 subsets x top-2 -> top-4 per row (block-wide)
    struct Pair { uint32_t v; int i; };
    Pair* pr = reinterpret_cast<Pair*>(smem);   // reuse A region (reads done)
    const int l3 = lane & 3;
    __syncthreads();
#pragma unroll
    for (int rs = 0; rs < 8; ++rs) {
        int r = wm * 64 + (rs >> 1) * 16 + (lane >> 2) + (rs & 1) * 8;
        int sub = wn * 4 + l3;
        pr[r * 32 + sub * 2 + 0] = { p0[rs] & 0xFFFFFE00u, dec9(p0[rs], wn, l3) };
        pr[r * 32 + sub * 2 + 1] = { p1[rs] & 0xFFFFFE00u, dec9(p1[rs], wn, l3) };
    }
    __syncthreads();
    if (tid < 128) {
        uint32_t bv[4] = {0xFFFFFFFFu, 0xFFFFFFFFu, 0xFFFFFFFFu, 0xFFFFFFFFu};
        int      bi[4] = {0x7fffffff, 0x7fffffff, 0x7fffffff, 0x7fffffff};
        for (int j = 0; j < 32; ++j) {
            uint32_t v = pr[tid * 32 + j].v;
            int      i = pr[tid * 32 + j].i;
            if (v < bv[3] || (v == bv[3] && i < bi[3])) {
                if (v < bv[0] || (v == bv[0] && i < bi[0])) {
                    bv[3]=bv[2]; bi[3]=bi[2]; bv[2]=bv[1]; bi[2]=bi[1];
                    bv[1]=bv[0]; bi[1]=bi[0]; bv[0]=v; bi[0]=i;
                } else if (v < bv[1] || (v == bv[1] && i < bi[1])) {
                    bv[3]=bv[2]; bi[3]=bi[2]; bv[2]=bv[1]; bi[2]=bi[1];
                    bv[1]=v; bi[1]=i;
                } else if (v < bv[2] || (v == bv[2] && i < bi[2])) {
                    bv[3]=bv[2]; bi[3]=bi[2]; bv[2]=v; bi[2]=i;
                } else {
                    bv[3]=v; bi[3]=i;
                }
            }
        }
        int row = blockIdx.x * 128 + tid;
#pragma unroll
        for (int s = 0; s < 4; ++s) g_top4[row * 4 + s] = bi[s];
    }
}

// ---------------------------------------------------------------- kernel 5: fused exact rescore + gather + loss partials
// Reads the ORIGINAL latents coalesced (32 consecutive w per d-row) — no latF.
#define SMF_Z 0
#define SMF_E (32 * 257)
#define SMF_TOTAL ((2 * 32 * 257 + 32 + 256) * 4)
__global__ __launch_bounds__(256)
void rescore_gather_kernel(const float* __restrict__ lat,
                           float* __restrict__ out, float* __restrict__ out_idx_f) {
    extern __shared__ float sm[];
    float* zt = sm + SMF_Z;            // [32 w][257 d] fp32 latents
    float* et = sm + SMF_E;            // [32 w][257 d] gathered embeddings
    int*   sidx = (int*)(sm + 2 * 32 * 257);
    float* red  = sm + 2 * 32 * 257 + 32;

    int bh = blockIdx.x;               // (b,h)
    int b = bh >> 5, h = bh & 31;
    int t = threadIdx.x;
    int w = t & 31, dq = t >> 5;

    // load z tile from original layout: lat[b][d][h*32+w], coalesced over w
    size_t base = (size_t)b * (D_ * HW) + h * 32;
#pragma unroll 4
    for (int i = 0; i < 32; ++i) {
        int d = i * 8 + dq;
        zt[w * 257 + d] = lat[base + (size_t)d * HW + w];
    }
    __syncthreads();

    // phase 1: exact fp32 rescore — 8 threads per row
    {
        int rl = t >> 3, l8 = t & 7;
        int row = bh * 32 + rl;
        int cand[4];
#pragma unroll
        for (int c = 0; c < 4; ++c) cand[c] = g_top4[row * 4 + c];
        float dot[4] = {0.f, 0.f, 0.f, 0.f};
        for (int d = l8; d < D_; d += 8) {
            float zv = zt[rl * 257 + d];
#pragma unroll
            for (int c = 0; c < 4; ++c)
                dot[c] = fmaf(zv, g_embT[(size_t)cand[c] * D_ + d], dot[c]);
        }
#pragma unroll
        for (int c = 0; c < 4; ++c) {
#pragma unroll
            for (int off = 4; off > 0; off >>= 1)
                dot[c] += __shfl_down_sync(0xffffffffu, dot[c], off, 8);
        }
        if (l8 == 0) {
            float bv = FLT_MAX; int bi = 0x7fffffff;
#pragma unroll
            for (int c = 0; c < 4; ++c) {
                float dist = fmaf(-2.f, dot[c], g_enorm[cand[c]]);  // bias: invariant
                if (dist < bv || (dist == bv && cand[c] < bi)) { bv = dist; bi = cand[c]; }
            }
            g_idx[row] = bi;
            sidx[rl] = bi;
            out_idx_f[row] = (float)bi;
        }
    }
    __syncthreads();

    // gathered embedding rows (coalesced over d)
#pragma unroll 4
    for (int i = 0; i < 32; ++i)
        et[i * 257 + t] = g_embT[(size_t)sidx[i] * D_ + t];
    __syncthreads();

    // phase 2: write output coalesced over w; fused loss partials
    float lsum = 0.f;
#pragma unroll 4
    for (int i = 0; i < 32; ++i) {
        int d = i * 8 + dq;
        float v = et[w * 257 + d];
        float x = zt[w * 257 + d];
        out[base + (size_t)d * HW + w] = v;
        float df = v - x;
        lsum = fmaf(df, df, lsum);
    }
    red[t] = lsum;
    __syncthreads();
    for (int st = 128; st > 0; st >>= 1) {
        if (t < st) red[t] += red[t + st];
        __syncthreads();
    }
    if (t == 0) g_part[bh] = red[0];
}

// ---------------------------------------------------------------- kernel 6: final loss
__global__ void loss_kernel(float* __restrict__ out_loss) {
    __shared__ float red[1024];
    int t = threadIdx.x;
    red[t] = g_part[t];
    __syncthreads();
    for (int st = 512; st > 0; st >>= 1) {
        if (t < st) red[t] += red[t + st];
        __syncthreads();
    }
    if (t == 0) out_loss[0] = 1.25f * (red[0] / 8388608.0f);
}

// ----------------------------------------------------------------
extern "C" void kernel_launch(void* const* d_in, const int* in_sizes, int n_in,
                              void* d_out, int out_size) {
    const float* lat = (const float*)d_in[0];
    const float* emb = (const float*)d_in[1];
    if (n_in >= 2 && in_sizes[0] == D_ * K_) {   // defensive size-based ident
        lat = (const float*)d_in[1];
        emb = (const float*)d_in[0];
    }
    float* out = (float*)d_out;

    embprep_kernel<<<K_ / 256, 256>>>(emb);
    latconv_kernel<<<dim3(HW / 32, D_ / 32, B_), dim3(32, 32)>>>(lat);
    embT_kernel<<<dim3(K_ / 32, D_ / 32), dim3(32, 32)>>>(emb);

    // vq_mma stays the 4th launch so ncu's skip window profiles it.
    cudaFuncSetAttribute(vq_mma_kernel,
                         cudaFuncAttributeMaxDynamicSharedMemorySize, SM_TOTAL);
    vq_mma_kernel<<<N_ / 128, 256, SM_TOTAL>>>();

    cudaFuncSetAttribute(rescore_gather_kernel,
                         cudaFuncAttributeMaxDynamicSharedMemorySize, SMF_TOTAL);
    rescore_gather_kernel<<<B_ * 32, 256, SMF_TOTAL>>>(lat, out, out + IDX_OFF);
    loss_kernel<<<1, 1024>>>(out + LOSS_OFF);
}